// round 7
// baseline (speedup 1.0000x reference)
#include <cuda_runtime.h>
#include <cstdint>

// TPThird: e3nn-style tensor product, Z=50000 samples.
// x1: (Z,108) = [0e:48 | 1o:10x3 | 1e:10x3], x2: (Z,9) = [0e | 1o:3 | 2e:5]
// weights: (Z,4344), out: (Z,156) = [r0e:48 | r1o:30 | r1e:30 | r0o:48]
//
// Non-persistent blocks, 2 samples per block; both samples' weight blobs are
// put in flight via cp.async.bulk immediately at block start (two buffers,
// two mbarriers). Sample 0's compute hides sample 1's copy latency.

#define NS 48
#define NV 10
#define WNUM 4344
#define WBYTES (WNUM * 4)
#define OUTDIM 156
#define SPB 2              // samples per block

#define OFF_W00   0
#define OFF_W01   2304
#define OFF_W10   2784
#define OFF_W110  2884
#define OFF_W112  3364
#define OFF_W12   3464
#define OFF_W20   3564
#define OFF_W211  3664
#define OFF_W213  3764
#define OFF_W22   4244

#define N0E  0.13130643285972254f   // sqrt(1/58)
#define N1O  0.19611613513818404f   // sqrt(3/78)
#define N1E  0.31622776601683794f   // sqrt(1/10)
#define N0O  0.31622776601683794f   // sqrt(1/10)
#define ISQ3 0.57735026918962576f   // 1/sqrt(3)
#define ISQ6 0.40824829046386302f   // 1/sqrt(6)
#define S10  0.31622776601683794f   // 1/sqrt(10)
#define S30  0.18257418583505537f   // 1/sqrt(30)

__device__ __forceinline__ uint32_t smem_u32(const void* p) {
    uint32_t a;
    asm("{ .reg .u64 t; cvta.to.shared.u64 t, %1; cvt.u32.u64 %0, t; }"
        : "=r"(a) : "l"(p));
    return a;
}

__device__ __forceinline__ void tma_issue(uint32_t dst, const void* src,
                                          uint32_t mbar_a) {
    asm volatile("mbarrier.arrive.expect_tx.shared.b64 _, [%0], %1;"
                 :: "r"(mbar_a), "r"((uint32_t)WBYTES) : "memory");
    asm volatile(
        "cp.async.bulk.shared::cluster.global.mbarrier::complete_tx::bytes "
        "[%0], [%1], %2, [%3];"
        :: "r"(dst), "l"(src), "r"((uint32_t)WBYTES), "r"(mbar_a)
        : "memory");
}

__device__ __forceinline__ void mbar_wait(uint32_t mbar_a) {
    asm volatile(
        "{\n\t"
        ".reg .pred P;\n\t"
        "WAIT_%=:\n\t"
        "mbarrier.try_wait.parity.acquire.cta.shared::cta.b64 P, [%0], 0, 0x989680;\n\t"
        "@!P bra WAIT_%=;\n\t"
        "}"
        :: "r"(mbar_a) : "memory");
}

__global__ __launch_bounds__(192) void tp_third_kernel(
    const float* __restrict__ x1,
    const float* __restrict__ x2,
    const float* __restrict__ wts,
    float* __restrict__ out,
    int Z)
{
    const int t = threadIdx.x;
    const int z0 = blockIdx.x * SPB;

    __shared__ alignas(128) float sw[SPB][WNUM];   // 2 x 17376 B weight buffers
    __shared__ alignas(8) unsigned long long mbar[SPB];
    __shared__ float sx1[SPB][108];
    __shared__ float sx2[SPB][9];
    __shared__ float s_a00[SPB][48];
    __shared__ float s_a110[SPB][10];
    __shared__ float s_a213[SPB][10];
    __shared__ float s_v10[SPB][30];
    __shared__ float s_v12[SPB][30];
    __shared__ float s_v211[SPB][30];
    __shared__ float s_v112[SPB][30];
    __shared__ float s_v20[SPB][30];
    __shared__ float s_v22[SPB][30];

    const int nsmp = (Z - z0 < SPB) ? (Z - z0) : SPB;
    if (nsmp <= 0) return;

    // ---- init mbarriers, then put BOTH weight blobs in flight ----
    if (t < nsmp) {
        asm volatile("mbarrier.init.shared.b64 [%0], 1;"
                     :: "r"(smem_u32(&mbar[t])) : "memory");
    }
    __syncthreads();
    if (t < nsmp) {
        tma_issue(smem_u32(sw[t]),
                  (const void*)(wts + (size_t)(z0 + t) * WNUM),
                  smem_u32(&mbar[t]));
    }

    // ---- stage small inputs for both samples (concurrent with copies) ----
    // FIX vs R6: full coverage of SPB*108 x1 floats via strided loop.
    for (int i = t; i < SPB * 108; i += 192) {
        const int s = i / 108, ii = i - s * 108;
        if (s < nsmp) sx1[s][ii] = x1[(size_t)(z0 + s) * 108 + ii];
    }
    if (t < SPB * 9) {
        const int s = t / 9, i = t - s * 9;
        if (s < nsmp) sx2[s][i] = x2[(size_t)(z0 + s) * 9 + i];
    }
    __syncthreads();

    // ---- phase 2: left-operand vectors for both samples ----
    // threads [0,96) -> sample 0, [96,192) -> sample 1 (first 68 of each
    // 96-group active)
    {
        const int s  = t / 96;
        const int tt = t - s * 96;
        if (s < nsmp) {
            const float e0 = sx2[s][0];
            const float b0 = sx2[s][1], b1 = sx2[s][2], b2 = sx2[s][3];
            const float c0 = sx2[s][4], c1 = sx2[s][5], c2 = sx2[s][6],
                        c3 = sx2[s][7], c4 = sx2[s][8];
            if (tt < 48) {
                s_a00[s][tt] = N0E * e0 * sx1[s][tt];
            } else if (tt < 58) {
                const int u = tt - 48;
                const float a0 = sx1[s][48 + u * 3 + 0];
                const float a1 = sx1[s][48 + u * 3 + 1];
                const float a2 = sx1[s][48 + u * 3 + 2];
                s_a110[s][u] = N0E * ISQ3 * (a0 * b0 + a1 * b1 + a2 * b2);
                s_v10[s][u * 3 + 0] = N1O * ISQ3 * e0 * a0;
                s_v10[s][u * 3 + 1] = N1O * ISQ3 * e0 * a1;
                s_v10[s][u * 3 + 2] = N1O * ISQ3 * e0 * a2;
                s_v112[s][u * 3 + 0] = N1E * ISQ6 * (a1 * b2 - a2 * b1);
                s_v112[s][u * 3 + 1] = N1E * ISQ6 * (a2 * b0 - a0 * b2);
                s_v112[s][u * 3 + 2] = N1E * ISQ6 * (a0 * b1 - a1 * b0);
                const float g0 = S10 * a2 * c0 - S30 * a0 * c2 - S10 * a0 * c4 + S10 * a1 * c1;
                const float g1 = S10 * a2 * c3 + S10 * a0 * c1 + 2.0f * S30 * a1 * c2;
                const float g2 = -S30 * a2 * c2 + S10 * a2 * c4 + S10 * a0 * c0 + S10 * a1 * c3;
                s_v12[s][u * 3 + 0] = N1O * g0;
                s_v12[s][u * 3 + 1] = N1O * g1;
                s_v12[s][u * 3 + 2] = N1O * g2;
            } else if (tt < 68) {
                const int u = tt - 58;
                const float a0 = sx1[s][78 + u * 3 + 0];
                const float a1 = sx1[s][78 + u * 3 + 1];
                const float a2 = sx1[s][78 + u * 3 + 2];
                s_a213[s][u] = N0O * ISQ3 * (a0 * b0 + a1 * b1 + a2 * b2);
                s_v20[s][u * 3 + 0] = N1E * ISQ3 * e0 * a0;
                s_v20[s][u * 3 + 1] = N1E * ISQ3 * e0 * a1;
                s_v20[s][u * 3 + 2] = N1E * ISQ3 * e0 * a2;
                s_v211[s][u * 3 + 0] = N1O * ISQ6 * (a1 * b2 - a2 * b1);
                s_v211[s][u * 3 + 1] = N1O * ISQ6 * (a2 * b0 - a0 * b2);
                s_v211[s][u * 3 + 2] = N1O * ISQ6 * (a0 * b1 - a1 * b0);
                const float g0 = S10 * a2 * c0 - S30 * a0 * c2 - S10 * a0 * c4 + S10 * a1 * c1;
                const float g1 = S10 * a2 * c3 + S10 * a0 * c1 + 2.0f * S30 * a1 * c2;
                const float g2 = -S30 * a2 * c2 + S10 * a2 * c4 + S10 * a0 * c0 + S10 * a1 * c3;
                s_v22[s][u * 3 + 0] = N1E * g0;
                s_v22[s][u * 3 + 1] = N1E * g1;
                s_v22[s][u * 3 + 2] = N1E * g2;
            }
        }
    }
    __syncthreads();

    // ---- phase 3: per-sample compute; wait only for that sample's blob ----
    #pragma unroll
    for (int k = 0; k < SPB; k++) {
        if (k >= nsmp) break;
        mbar_wait(smem_u32(&mbar[k]));

        const float* __restrict__ W = sw[k];
        float* __restrict__ o = out + (size_t)(z0 + k) * OUTDIM;

        if (t < 64) {
            if (t < 48) {
                const int w = t;
                float acc = 0.0f;
                #pragma unroll
                for (int u = 0; u < 48; u++) acc += s_a00[k][u] * W[OFF_W00 + u * 48 + w];
                #pragma unroll
                for (int u = 0; u < 10; u++) acc += s_a110[k][u] * W[OFF_W110 + u * 48 + w];
                o[w] = acc;
            }
        } else if (t < 128) {
            const int w = t - 64;
            if (w < 48) {
                float acc = 0.0f;
                #pragma unroll
                for (int u = 0; u < 10; u++) acc += s_a213[k][u] * W[OFF_W213 + u * 48 + w];
                o[108 + w] = acc;
            }
        } else if (t < 160) {
            const int idx = t - 128;
            const int w = idx / 3, j = idx - w * 3;
            const int wc = (w > 9) ? 9 : w;
            float p = 0.0f;
            #pragma unroll
            for (int i = 0; i < 16; i++) {
                const int u = 3 * i + j;
                p += sx1[k][u] * W[OFF_W01 + u * 10 + wc];
            }
            const int base = w * 3;
            float ts = __shfl_sync(0xFFFFFFFFu, p, base)
                     + __shfl_sync(0xFFFFFFFFu, p, base + 1)
                     + __shfl_sync(0xFFFFFFFFu, p, base + 2);
            float acc = (N1O * ISQ3) * sx2[k][1 + j] * ts;
            #pragma unroll
            for (int u = 0; u < 10; u++) {
                acc += s_v10[k][u * 3 + j]  * W[OFF_W10  + u * 10 + wc];
                acc += s_v12[k][u * 3 + j]  * W[OFF_W12  + u * 10 + wc];
                acc += s_v211[k][u * 3 + j] * W[OFF_W211 + u * 10 + wc];
            }
            if (idx < 30) o[48 + w * 3 + j] = acc;
        } else {
            const int idx = t - 160;
            if (idx < 30) {
                const int w = idx / 3, j = idx - w * 3;
                float acc = 0.0f;
                #pragma unroll
                for (int u = 0; u < 10; u++) {
                    acc += s_v112[k][u * 3 + j] * W[OFF_W112 + u * 10 + w];
                    acc += s_v20[k][u * 3 + j]  * W[OFF_W20  + u * 10 + w];
                    acc += s_v22[k][u * 3 + j]  * W[OFF_W22  + u * 10 + w];
                }
                o[78 + w * 3 + j] = acc;
            }
        }
    }
}

extern "C" void kernel_launch(void* const* d_in, const int* in_sizes, int n_in,
                              void* d_out, int out_size) {
    const float* x1  = (const float*)d_in[0];
    const float* x2  = (const float*)d_in[1];
    const float* wts = (const float*)d_in[2];
    float* out = (float*)d_out;
    const int Z = in_sizes[0] / 108;
    const int grid = (Z + SPB - 1) / SPB;
    tp_third_kernel<<<grid, 192>>>(x1, x2, wts, out, Z);
}

// round 8
// speedup vs baseline: 1.2393x; 1.2393x over previous
#include <cuda_runtime.h>
#include <cstdint>

// TPThird: e3nn-style tensor product, Z=50000 samples.
// x1: (Z,108) = [0e:48 | 1o:10x3 | 1e:10x3], x2: (Z,9) = [0e | 1o:3 | 2e:5]
// weights: (Z,4344), out: (Z,156) = [r0e:48 | r1o:30 | r1e:30 | r0o:48]
//
// R4 shape (1 sample per block, TMA bulk weight copy into smem) with the
// copy issued at block entry with no intervening __syncthreads, and
// streaming stores for the output.

#define NS 48
#define NV 10
#define WNUM 4344
#define WBYTES (WNUM * 4)
#define OUTDIM 156

#define OFF_W00   0
#define OFF_W01   2304
#define OFF_W10   2784
#define OFF_W110  2884
#define OFF_W112  3364
#define OFF_W12   3464
#define OFF_W20   3564
#define OFF_W211  3664
#define OFF_W213  3764
#define OFF_W22   4244

#define N0E  0.13130643285972254f   // sqrt(1/58)
#define N1O  0.19611613513818404f   // sqrt(3/78)
#define N1E  0.31622776601683794f   // sqrt(1/10)
#define N0O  0.31622776601683794f   // sqrt(1/10)
#define ISQ3 0.57735026918962576f   // 1/sqrt(3)
#define ISQ6 0.40824829046386302f   // 1/sqrt(6)
#define S10  0.31622776601683794f   // 1/sqrt(10)
#define S30  0.18257418583505537f   // 1/sqrt(30)

__device__ __forceinline__ uint32_t smem_u32(const void* p) {
    uint32_t a;
    asm("{ .reg .u64 t; cvta.to.shared.u64 t, %1; cvt.u32.u64 %0, t; }"
        : "=r"(a) : "l"(p));
    return a;
}

__global__ __launch_bounds__(192) void tp_third_kernel(
    const float* __restrict__ x1,
    const float* __restrict__ x2,
    const float* __restrict__ wts,
    float* __restrict__ out)
{
    const int z = blockIdx.x;
    const int t = threadIdx.x;

    __shared__ alignas(128) float sw[WNUM];   // 17376 B weight stage
    __shared__ alignas(8) unsigned long long mbar;
    __shared__ float sx1[108];
    __shared__ float sx2[9];
    __shared__ float s_a00[48];
    __shared__ float s_a110[10];
    __shared__ float s_a213[10];
    __shared__ float s_v10[30];
    __shared__ float s_v12[30];
    __shared__ float s_v211[30];
    __shared__ float s_v112[30];
    __shared__ float s_v20[30];
    __shared__ float s_v22[30];

    // ---- thread 0: init barrier + issue bulk copy IMMEDIATELY (no sync
    //      needed: only thread 0 touches the mbarrier until the wait, which
    //      is ordered behind the phase-2 __syncthreads) ----
    if (t == 0) {
        const uint32_t mbar_a = smem_u32(&mbar);
        asm volatile("mbarrier.init.shared.b64 [%0], 1;" :: "r"(mbar_a) : "memory");
        asm volatile("fence.proxy.async.shared::cta;" ::: "memory");
        asm volatile("mbarrier.arrive.expect_tx.shared.b64 _, [%0], %1;"
                     :: "r"(mbar_a), "r"((uint32_t)WBYTES) : "memory");
        asm volatile(
            "cp.async.bulk.shared::cluster.global.mbarrier::complete_tx::bytes "
            "[%0], [%1], %2, [%3];"
            :: "r"(smem_u32(sw)),
               "l"((const void*)(wts + (size_t)z * WNUM)),
               "r"((uint32_t)WBYTES), "r"(mbar_a)
            : "memory");
    }

    // ---- stage small inputs concurrently with the copy ----
    if (t >= 32 && t < 140)       sx1[t - 32]  = x1[(size_t)z * 108 + (t - 32)];
    else if (t >= 140 && t < 149) sx2[t - 140] = x2[(size_t)z * 9 + (t - 140)];
    __syncthreads();

    // ---- phase 2: left-operand vectors (overlaps TMA) ----
    const float e0 = sx2[0];
    const float b0 = sx2[1], b1 = sx2[2], b2 = sx2[3];
    const float c0 = sx2[4], c1 = sx2[5], c2 = sx2[6], c3 = sx2[7], c4 = sx2[8];

    if (t < 48) {
        s_a00[t] = N0E * e0 * sx1[t];
    } else if (t < 58) {
        const int u = t - 48;
        const float a0 = sx1[48 + u * 3 + 0];
        const float a1 = sx1[48 + u * 3 + 1];
        const float a2 = sx1[48 + u * 3 + 2];
        s_a110[u] = N0E * ISQ3 * (a0 * b0 + a1 * b1 + a2 * b2);
        s_v10[u * 3 + 0] = N1O * ISQ3 * e0 * a0;
        s_v10[u * 3 + 1] = N1O * ISQ3 * e0 * a1;
        s_v10[u * 3 + 2] = N1O * ISQ3 * e0 * a2;
        s_v112[u * 3 + 0] = N1E * ISQ6 * (a1 * b2 - a2 * b1);
        s_v112[u * 3 + 1] = N1E * ISQ6 * (a2 * b0 - a0 * b2);
        s_v112[u * 3 + 2] = N1E * ISQ6 * (a0 * b1 - a1 * b0);
        const float g0 = S10 * a2 * c0 - S30 * a0 * c2 - S10 * a0 * c4 + S10 * a1 * c1;
        const float g1 = S10 * a2 * c3 + S10 * a0 * c1 + 2.0f * S30 * a1 * c2;
        const float g2 = -S30 * a2 * c2 + S10 * a2 * c4 + S10 * a0 * c0 + S10 * a1 * c3;
        s_v12[u * 3 + 0] = N1O * g0;
        s_v12[u * 3 + 1] = N1O * g1;
        s_v12[u * 3 + 2] = N1O * g2;
    } else if (t < 68) {
        const int u = t - 58;
        const float a0 = sx1[78 + u * 3 + 0];
        const float a1 = sx1[78 + u * 3 + 1];
        const float a2 = sx1[78 + u * 3 + 2];
        s_a213[u] = N0O * ISQ3 * (a0 * b0 + a1 * b1 + a2 * b2);
        s_v20[u * 3 + 0] = N1E * ISQ3 * e0 * a0;
        s_v20[u * 3 + 1] = N1E * ISQ3 * e0 * a1;
        s_v20[u * 3 + 2] = N1E * ISQ3 * e0 * a2;
        s_v211[u * 3 + 0] = N1O * ISQ6 * (a1 * b2 - a2 * b1);
        s_v211[u * 3 + 1] = N1O * ISQ6 * (a2 * b0 - a0 * b2);
        s_v211[u * 3 + 2] = N1O * ISQ6 * (a0 * b1 - a1 * b0);
        const float g0 = S10 * a2 * c0 - S30 * a0 * c2 - S10 * a0 * c4 + S10 * a1 * c1;
        const float g1 = S10 * a2 * c3 + S10 * a0 * c1 + 2.0f * S30 * a1 * c2;
        const float g2 = -S30 * a2 * c2 + S10 * a2 * c4 + S10 * a0 * c0 + S10 * a1 * c3;
        s_v22[u * 3 + 0] = N1E * g0;
        s_v22[u * 3 + 1] = N1E * g1;
        s_v22[u * 3 + 2] = N1E * g2;
    }
    __syncthreads();

    // ---- wait for weight blob ----
    {
        const uint32_t mbar_a = smem_u32(&mbar);
        asm volatile(
            "{\n\t"
            ".reg .pred P;\n\t"
            "WAIT_%=:\n\t"
            "mbarrier.try_wait.parity.acquire.cta.shared::cta.b64 P, [%0], 0, 0x989680;\n\t"
            "@!P bra WAIT_%=;\n\t"
            "}"
            :: "r"(mbar_a) : "memory");
    }

    // ---- phase 3: column matvecs from smem, warp-aligned output groups ----
    float* __restrict__ o = out + (size_t)z * OUTDIM;

    if (t < 64) {
        if (t < 48) {
            const int w = t;
            float acc = 0.0f;
            #pragma unroll
            for (int u = 0; u < 48; u++) acc += s_a00[u] * sw[OFF_W00 + u * 48 + w];
            #pragma unroll
            for (int u = 0; u < 10; u++) acc += s_a110[u] * sw[OFF_W110 + u * 48 + w];
            __stcs(&o[w], acc);
        }
    } else if (t < 128) {
        const int w = t - 64;
        if (w < 48) {
            float acc = 0.0f;
            #pragma unroll
            for (int u = 0; u < 10; u++) acc += s_a213[u] * sw[OFF_W213 + u * 48 + w];
            __stcs(&o[108 + w], acc);
        }
    } else if (t < 160) {
        const int idx = t - 128;
        const int w = idx / 3, j = idx - w * 3;
        const int wc = (w > 9) ? 9 : w;
        float p = 0.0f;
        #pragma unroll
        for (int i = 0; i < 16; i++) {
            const int u = 3 * i + j;
            p += sx1[u] * sw[OFF_W01 + u * 10 + wc];
        }
        const int base = w * 3;
        float ts = __shfl_sync(0xFFFFFFFFu, p, base)
                 + __shfl_sync(0xFFFFFFFFu, p, base + 1)
                 + __shfl_sync(0xFFFFFFFFu, p, base + 2);
        float acc = (N1O * ISQ3) * sx2[1 + j] * ts;
        #pragma unroll
        for (int u = 0; u < 10; u++) {
            acc += s_v10[u * 3 + j]  * sw[OFF_W10  + u * 10 + wc];
            acc += s_v12[u * 3 + j]  * sw[OFF_W12  + u * 10 + wc];
            acc += s_v211[u * 3 + j] * sw[OFF_W211 + u * 10 + wc];
        }
        if (idx < 30) __stcs(&o[48 + w * 3 + j], acc);
    } else {
        const int idx = t - 160;
        if (idx < 30) {
            const int w = idx / 3, j = idx - w * 3;
            float acc = 0.0f;
            #pragma unroll
            for (int u = 0; u < 10; u++) {
                acc += s_v112[u * 3 + j] * sw[OFF_W112 + u * 10 + w];
                acc += s_v20[u * 3 + j]  * sw[OFF_W20  + u * 10 + w];
                acc += s_v22[u * 3 + j]  * sw[OFF_W22  + u * 10 + w];
            }
            __stcs(&o[78 + w * 3 + j], acc);
        }
    }
}

extern "C" void kernel_launch(void* const* d_in, const int* in_sizes, int n_in,
                              void* d_out, int out_size) {
    const float* x1  = (const float*)d_in[0];
    const float* x2  = (const float*)d_in[1];
    const float* wts = (const float*)d_in[2];
    float* out = (float*)d_out;
    const int Z = in_sizes[0] / 108;
    tp_third_kernel<<<Z, 192>>>(x1, x2, wts, out);
}

// round 12
// speedup vs baseline: 1.2479x; 1.0070x over previous
#include <cuda_runtime.h>
#include <cstdint>

// TPThird: e3nn-style tensor product, Z=50000 samples.
// x1: (Z,108) = [0e:48 | 1o:10x3 | 1e:10x3], x2: (Z,9) = [0e | 1o:3 | 2e:5]
// weights: (Z,4344), out: (Z,156) = [r0e:48 | r1o:30 | r1e:30 | r0o:48]
//
// 1 sample per block, TMA bulk weight copy into smem issued at block entry,
// streaming output stores. 160 threads/block -> 12 resident blocks/SM
// (vs 10 at 192): more concurrent TMA streams per SM.

#define NS 48
#define NV 10
#define WNUM 4344
#define WBYTES (WNUM * 4)
#define OUTDIM 156

#define OFF_W00   0
#define OFF_W01   2304
#define OFF_W10   2784
#define OFF_W110  2884
#define OFF_W112  3364
#define OFF_W12   3464
#define OFF_W20   3564
#define OFF_W211  3664
#define OFF_W213  3764
#define OFF_W22   4244

#define N0E  0.13130643285972254f   // sqrt(1/58)
#define N1O  0.19611613513818404f   // sqrt(3/78)
#define N1E  0.31622776601683794f   // sqrt(1/10)
#define N0O  0.31622776601683794f   // sqrt(1/10)
#define ISQ3 0.57735026918962576f   // 1/sqrt(3)
#define ISQ6 0.40824829046386302f   // 1/sqrt(6)
#define S10  0.31622776601683794f   // 1/sqrt(10)
#define S30  0.18257418583505537f   // 1/sqrt(30)

__device__ __forceinline__ uint32_t smem_u32(const void* p) {
    uint32_t a;
    asm("{ .reg .u64 t; cvta.to.shared.u64 t, %1; cvt.u32.u64 %0, t; }"
        : "=r"(a) : "l"(p));
    return a;
}

__global__ __launch_bounds__(160) void tp_third_kernel(
    const float* __restrict__ x1,
    const float* __restrict__ x2,
    const float* __restrict__ wts,
    float* __restrict__ out)
{
    const int z = blockIdx.x;
    const int t = threadIdx.x;

    __shared__ alignas(128) float sw[WNUM];   // 17376 B weight stage
    __shared__ alignas(8) unsigned long long mbar;
    __shared__ float sx1[108];
    __shared__ float sx2[9];
    __shared__ float s_a00[48];
    __shared__ float s_a110[10];
    __shared__ float s_a213[10];
    __shared__ float s_v10[30];
    __shared__ float s_v12[30];
    __shared__ float s_v211[30];
    __shared__ float s_v112[30];
    __shared__ float s_v20[30];
    __shared__ float s_v22[30];

    // ---- thread 0: init barrier + issue bulk copy IMMEDIATELY ----
    if (t == 0) {
        const uint32_t mbar_a = smem_u32(&mbar);
        asm volatile("mbarrier.init.shared.b64 [%0], 1;" :: "r"(mbar_a) : "memory");
        asm volatile("fence.proxy.async.shared::cta;" ::: "memory");
        asm volatile("mbarrier.arrive.expect_tx.shared.b64 _, [%0], %1;"
                     :: "r"(mbar_a), "r"((uint32_t)WBYTES) : "memory");
        asm volatile(
            "cp.async.bulk.shared::cluster.global.mbarrier::complete_tx::bytes "
            "[%0], [%1], %2, [%3];"
            :: "r"(smem_u32(sw)),
               "l"((const void*)(wts + (size_t)z * WNUM)),
               "r"((uint32_t)WBYTES), "r"(mbar_a)
            : "memory");
    }

    // ---- stage small inputs concurrently with the copy ----
    if (t >= 32 && t < 140)       sx1[t - 32]  = x1[(size_t)z * 108 + (t - 32)];
    else if (t >= 140 && t < 149) sx2[t - 140] = x2[(size_t)z * 9 + (t - 140)];
    __syncthreads();

    // ---- phase 2: left-operand vectors (overlaps TMA) ----
    const float e0 = sx2[0];
    const float b0 = sx2[1], b1 = sx2[2], b2 = sx2[3];
    const float c0 = sx2[4], c1 = sx2[5], c2 = sx2[6], c3 = sx2[7], c4 = sx2[8];

    if (t < 48) {
        s_a00[t] = N0E * e0 * sx1[t];
    } else if (t < 58) {
        const int u = t - 48;
        const float a0 = sx1[48 + u * 3 + 0];
        const float a1 = sx1[48 + u * 3 + 1];
        const float a2 = sx1[48 + u * 3 + 2];
        s_a110[u] = N0E * ISQ3 * (a0 * b0 + a1 * b1 + a2 * b2);
        s_v10[u * 3 + 0] = N1O * ISQ3 * e0 * a0;
        s_v10[u * 3 + 1] = N1O * ISQ3 * e0 * a1;
        s_v10[u * 3 + 2] = N1O * ISQ3 * e0 * a2;
        s_v112[u * 3 + 0] = N1E * ISQ6 * (a1 * b2 - a2 * b1);
        s_v112[u * 3 + 1] = N1E * ISQ6 * (a2 * b0 - a0 * b2);
        s_v112[u * 3 + 2] = N1E * ISQ6 * (a0 * b1 - a1 * b0);
        const float g0 = S10 * a2 * c0 - S30 * a0 * c2 - S10 * a0 * c4 + S10 * a1 * c1;
        const float g1 = S10 * a2 * c3 + S10 * a0 * c1 + 2.0f * S30 * a1 * c2;
        const float g2 = -S30 * a2 * c2 + S10 * a2 * c4 + S10 * a0 * c0 + S10 * a1 * c3;
        s_v12[u * 3 + 0] = N1O * g0;
        s_v12[u * 3 + 1] = N1O * g1;
        s_v12[u * 3 + 2] = N1O * g2;
    } else if (t < 68) {
        const int u = t - 58;
        const float a0 = sx1[78 + u * 3 + 0];
        const float a1 = sx1[78 + u * 3 + 1];
        const float a2 = sx1[78 + u * 3 + 2];
        s_a213[u] = N0O * ISQ3 * (a0 * b0 + a1 * b1 + a2 * b2);
        s_v20[u * 3 + 0] = N1E * ISQ3 * e0 * a0;
        s_v20[u * 3 + 1] = N1E * ISQ3 * e0 * a1;
        s_v20[u * 3 + 2] = N1E * ISQ3 * e0 * a2;
        s_v211[u * 3 + 0] = N1O * ISQ6 * (a1 * b2 - a2 * b1);
        s_v211[u * 3 + 1] = N1O * ISQ6 * (a2 * b0 - a0 * b2);
        s_v211[u * 3 + 2] = N1O * ISQ6 * (a0 * b1 - a1 * b0);
        const float g0 = S10 * a2 * c0 - S30 * a0 * c2 - S10 * a0 * c4 + S10 * a1 * c1;
        const float g1 = S10 * a2 * c3 + S10 * a0 * c1 + 2.0f * S30 * a1 * c2;
        const float g2 = -S30 * a2 * c2 + S10 * a2 * c4 + S10 * a0 * c0 + S10 * a1 * c3;
        s_v22[u * 3 + 0] = N1E * g0;
        s_v22[u * 3 + 1] = N1E * g1;
        s_v22[u * 3 + 2] = N1E * g2;
    }
    __syncthreads();

    // ---- wait for weight blob ----
    {
        const uint32_t mbar_a = smem_u32(&mbar);
        asm volatile(
            "{\n\t"
            ".reg .pred P;\n\t"
            "WAIT_%=:\n\t"
            "mbarrier.try_wait.parity.acquire.cta.shared::cta.b64 P, [%0], 0, 0x989680;\n\t"
            "@!P bra WAIT_%=;\n\t"
            "}"
            :: "r"(mbar_a) : "memory");
    }

    // ---- phase 3: column matvecs from smem; 5-warp mapping ----
    float* __restrict__ o = out + (size_t)z * OUTDIM;

    if (t < 64) {
        // warps 0-1: r0e[w] : w00 (48x48) + w110 (10x48)
        if (t < 48) {
            const int w = t;
            float acc = 0.0f;
            #pragma unroll
            for (int u = 0; u < 48; u++) acc += s_a00[u] * sw[OFF_W00 + u * 48 + w];
            #pragma unroll
            for (int u = 0; u < 10; u++) acc += s_a110[u] * sw[OFF_W110 + u * 48 + w];
            __stcs(&o[w], acc);
        }
    } else if (t < 96) {
        // warp 2: r0o[0..31]
        const int w = t - 64;
        float acc = 0.0f;
        #pragma unroll
        for (int u = 0; u < 10; u++) acc += s_a213[u] * sw[OFF_W213 + u * 48 + w];
        __stcs(&o[108 + w], acc);
    } else if (t < 128) {
        // warp 3: r0o[32..47] (lanes 0-15), then r1e (lanes 0-29)
        const int lane = t - 96;
        if (lane < 16) {
            const int w = 32 + lane;
            float acc = 0.0f;
            #pragma unroll
            for (int u = 0; u < 10; u++) acc += s_a213[u] * sw[OFF_W213 + u * 48 + w];
            __stcs(&o[108 + w], acc);
        }
        if (lane < 30) {
            const int w = lane / 3, j = lane - w * 3;
            float acc = 0.0f;
            #pragma unroll
            for (int u = 0; u < 10; u++) {
                acc += s_v112[u * 3 + j] * sw[OFF_W112 + u * 10 + w];
                acc += s_v20[u * 3 + j]  * sw[OFF_W20  + u * 10 + w];
                acc += s_v22[u * 3 + j]  * sw[OFF_W22  + u * 10 + w];
            }
            __stcs(&o[78 + w * 3 + j], acc);
        }
    } else {
        // warp 4: r1o[w,j] : w01 (48x10) split over j via shuffle + w10/w12/w211
        const int idx = t - 128;
        const int w = idx / 3, j = idx - w * 3;
        const int wc = (w > 9) ? 9 : w;
        float p = 0.0f;
        #pragma unroll
        for (int i = 0; i < 16; i++) {
            const int u = 3 * i + j;
            p += sx1[u] * sw[OFF_W01 + u * 10 + wc];
        }
        const int base = w * 3;
        float ts = __shfl_sync(0xFFFFFFFFu, p, base)
                 + __shfl_sync(0xFFFFFFFFu, p, base + 1)
                 + __shfl_sync(0xFFFFFFFFu, p, base + 2);
        float acc = (N1O * ISQ3) * sx2[1 + j] * ts;
        #pragma unroll
        for (int u = 0; u < 10; u++) {
            acc += s_v10[u * 3 + j]  * sw[OFF_W10  + u * 10 + wc];
            acc += s_v12[u * 3 + j]  * sw[OFF_W12  + u * 10 + wc];
            acc += s_v211[u * 3 + j] * sw[OFF_W211 + u * 10 + wc];
        }
        if (idx < 30) __stcs(&o[48 + w * 3 + j], acc);
    }
}

extern "C" void kernel_launch(void* const* d_in, const int* in_sizes, int n_in,
                              void* d_out, int out_size) {
    const float* x1  = (const float*)d_in[0];
    const float* x2  = (const float*)d_in[1];
    const float* wts = (const float*)d_in[2];
    float* out = (float*)d_out;
    const int Z = in_sizes[0] / 108;
    tp_third_kernel<<<Z, 160>>>(x1, x2, wts, out);
}